// round 5
// baseline (speedup 1.0000x reference)
#include <cuda_runtime.h>

#define HH 60
#define WW 60
#define DDZ 36
#define NP 2048
#define NC 13
#define GRID_SZ 0.08f

#define TX 4
#define TY 8
#define TZ 8          // tile z extent (each compute thread: z and z+4)
#define TZS 4
#define TPB 256       // 2 halves x 128 compute lanes
#define HALF 128
#define BATCH 256

#define NTILE_X (HH / TX)                 // 15
#define NTILE_Y ((WW + TY - 1) / TY)      // 8
#define NTILE_Z ((DDZ + TZ - 1) / TZ)     // 5
#define NTILES (NTILE_X * NTILE_Y * NTILE_Z)  // 600
#define NBLOCKS 592                       // 4 per SM on 148 SMs

typedef unsigned long long ull;

// Per-Gaussian precomputed scratch (device globals: no allocation allowed)
__device__ int4   g_box[NP];       // bx, by, bz, r
__device__ float4 g_q0[NP];        // -0.5*ixx, -0.5*iyy, -0.5*izz, pad
__device__ float4 g_q1[NP];        // -ixy, -iyz, -ixz, mx
__device__ float2 g_q2[NP];        // my, mz
__device__ float4 g_sem4[NP][4];   // opacity * semantics, padded 13 -> 16
__device__ int    g_ctr;           // dynamic tile queue head

__device__ __forceinline__ ull bcast2(float v) {
    ull r; asm("mov.b64 %0, {%1, %1};" : "=l"(r) : "f"(v)); return r;
}
__device__ __forceinline__ ull fma2(ull a, ull b, ull c) {
    ull d; asm("fma.rn.f32x2 %0, %1, %2, %3;" : "=l"(d) : "l"(a), "l"(b), "l"(c)); return d;
}
__device__ __forceinline__ ull add2(ull a, ull b) {
    ull d; asm("add.rn.f32x2 %0, %1, %2;" : "=l"(d) : "l"(a), "l"(b)); return d;
}
__device__ __forceinline__ float2 unpack2(ull v) {
    float2 f; asm("mov.b64 {%0, %1}, %2;" : "=f"(f.x), "=f"(f.y) : "l"(v)); return f;
}

__global__ void precompute_kernel(const float* __restrict__ means3D,
                                  const float* __restrict__ opac,
                                  const float* __restrict__ semantics,
                                  const float* __restrict__ scales,
                                  const float* __restrict__ cov3D,
                                  const float* __restrict__ origin)
{
    int g = blockIdx.x * blockDim.x + threadIdx.x;
    if (g == 0) g_ctr = 0;           // reset dynamic queue every launch
    if (g >= NP) return;

    const float* cv = cov3D + g * 9;
    float a = cv[0], b = cv[4], c = cv[8];
    float d = cv[1], e = cv[5], f = cv[2];
    float det = a * (b * c - e * e) - d * (d * c - e * f) + f * (d * e - b * f);
    float ixx = (b * c - e * e) / det;
    float iyy = (a * c - f * f) / det;
    float izz = (a * b - d * d) / det;
    float ixy = (e * f - d * c) / det;
    float iyz = (d * f - a * e) / det;
    float ixz = (d * e - b * f) / det;

    float ox = origin[0], oy = origin[1], oz = origin[2];
    float mx = means3D[g * 3 + 0];
    float my = means3D[g * 3 + 1];
    float mz = means3D[g * 3 + 2];

    float s = fmaxf(scales[g * 3 + 0], fmaxf(scales[g * 3 + 1], scales[g * 3 + 2]));
    int r = (int)ceilf(s * 3.0f / GRID_SZ);

    g_box[g] = make_int4((int)((mx - ox) / GRID_SZ),
                         (int)((my - oy) / GRID_SZ),
                         (int)((mz - oz) / GRID_SZ), r);
    g_q0[g] = make_float4(-0.5f * ixx, -0.5f * iyy, -0.5f * izz, 0.0f);
    g_q1[g] = make_float4(-ixy, -iyz, -ixz, mx);
    g_q2[g] = make_float2(my, mz);

    float op = opac[g];
    float sv[16];
#pragma unroll
    for (int cc = 0; cc < NC; cc++) sv[cc] = op * semantics[g * NC + cc];
#pragma unroll
    for (int cc = NC; cc < 16; cc++) sv[cc] = 0.0f;
#pragma unroll
    for (int q = 0; q < 4; q++)
        g_sem4[g][q] = make_float4(sv[q*4], sv[q*4+1], sv[q*4+2], sv[q*4+3]);
}

__global__ __launch_bounds__(TPB, 4)
void aggregate_kernel(const float* __restrict__ pts,
                      const float* __restrict__ origin,
                      float* __restrict__ out)
{
    __shared__ int    s_tile;
    __shared__ int    s_cnt;
    __shared__ short  s_list[NP];
    __shared__ int4   s_box[BATCH];
    __shared__ float4 s_q0[BATCH];
    __shared__ float4 s_q1[BATCH];
    __shared__ float2 s_q2[BATCH];
    __shared__ float4 s_sem[BATCH][4];
    __shared__ ull    s_red[HALF][15];   // half-1 packed partials (14 used, odd stride)

    const int t    = threadIdx.x;
    const int half = t >> 7;             // 0 or 1
    const int tl   = t & (HALF - 1);

    const float ox = origin[0], oy = origin[1], oz = origin[2];

    for (;;) {
        if (t == 0) {
            s_tile = atomicAdd(&g_ctr, 1);
            s_cnt = 0;
        }
        __syncthreads();
        const int tile = s_tile;
        if (tile >= NTILES) break;

        const int bz = tile % NTILE_Z;
        const int by = (tile / NTILE_Z) % NTILE_Y;
        const int bxi = tile / (NTILE_Z * NTILE_Y);

        const int tlo_x = bxi * TX;
        const int tlo_y = by * TY;
        const int tlo_z = bz * TZ;
        const int thi_x = tlo_x + TX - 1;
        const int thi_y = min(tlo_y + TY - 1, WW - 1);
        const int thi_z = min(tlo_z + TZ - 1, DDZ - 1);

        // Cooperative coarse cull (all 256 threads)
        for (int g = t; g < NP; g += TPB) {
            int4 bxv = g_box[g];
            bool hit = (bxv.x - bxv.w <= thi_x) && (bxv.x + bxv.w >= tlo_x)
                    && (bxv.y - bxv.w <= thi_y) && (bxv.y + bxv.w >= tlo_y)
                    && (bxv.z - bxv.w <= thi_z) && (bxv.z + bxv.w >= tlo_z);
            if (hit) {
                int pos = atomicAdd(&s_cnt, 1);
                s_list[pos] = (short)g;
            }
        }
        __syncthreads();
        const int nlist = s_cnt;

        // Thread -> voxel pair
        const int tz = tl & (TZS - 1);
        const int ty = (tl >> 2) & (TY - 1);
        const int tx = tl >> 5;
        const int x  = tlo_x + tx;
        const int y  = tlo_y + ty;
        const int z0 = tlo_z + tz;
        const int z1 = z0 + TZS;
        const bool valid0 = (y < WW);
        const bool valid1 = valid0 && (z1 < DDZ);

        const int pidx0 = (x * WW + y) * DDZ + z0;
        const int pidx1 = pidx0 + TZS;

        float px = 0.f, py = 0.f, pz0 = 0.f, pz1 = 0.f;
        int pix = -100000, piy = -100000, piz0 = -100000, piz1 = -100000;
        if (valid0) {
            px  = pts[pidx0 * 3 + 0];
            py  = pts[pidx0 * 3 + 1];
            pz0 = pts[pidx0 * 3 + 2];
            pix  = (int)((px - ox) / GRID_SZ);
            piy  = (int)((py - oy) / GRID_SZ);
            piz0 = (int)((pz0 - oz) / GRID_SZ);
            if (valid1) {
                pz1  = pts[pidx1 * 3 + 2];
                piz1 = (int)((pz1 - oz) / GRID_SZ);
            }
        }

        // Packed channel-pair accumulators: 7 per voxel (13 ch + 1 pad)
        ull acc0p[7], acc1p[7];
#pragma unroll
        for (int k = 0; k < 7; k++) { acc0p[k] = 0ull; acc1p[k] = 0ull; }

        for (int base = 0; base < nlist; base += BATCH) {
            const int cnt = min(BATCH, nlist - base);

            if (t < cnt) {
                int g = s_list[base + t];
                s_box[t] = g_box[g];
                s_q0[t]  = g_q0[g];
                s_q1[t]  = g_q1[g];
                s_q2[t]  = g_q2[g];
#pragma unroll
                for (int q = 0; q < 4; q++) s_sem[t][q] = g_sem4[g][q];
            }
            __syncthreads();

            // Each half walks its own stride-2 subset of the staged batch
            for (int i = half; i < cnt; i += 2) {
                const int4 bxv = s_box[i];
                bool ibxy = (abs(pix - bxv.x) <= bxv.w) & (abs(piy - bxv.y) <= bxv.w);
                bool ib0 = ibxy & (abs(piz0 - bxv.z) <= bxv.w);
                bool ib1 = ibxy & (abs(piz1 - bxv.z) <= bxv.w);
                if (__any_sync(0xffffffffu, ib0 | ib1)) {
                    const float4 q1 = s_q1[i];
                    const float2 q2 = s_q2[i];
                    const float4 q0 = s_q0[i];
                    float dx  = px  - q1.w;
                    float dy  = py  - q2.x;
                    float dz0 = pz0 - q2.y;
                    float dz1 = pz1 - q2.y;
                    float exy = fmaf(q0.x * dx, dx, fmaf(q0.y * dy, dy, q1.x * dx * dy));
                    float h   = fmaf(q1.y, dy, q1.z * dx);
                    float e0  = fmaf(fmaf(q0.z, dz0, h), dz0, exy);
                    float e1  = fmaf(fmaf(q0.z, dz1, h), dz1, exy);
                    float w0 = ib0 ? __expf(e0) : 0.0f;
                    float w1 = ib1 ? __expf(e1) : 0.0f;
                    ull w0p = bcast2(w0);
                    ull w1p = bcast2(w1);
                    const ulonglong2* sp = (const ulonglong2*)(&s_sem[i][0]);
                    ulonglong2 sp0 = sp[0];   // ch 0-3
                    ulonglong2 sp1 = sp[1];   // ch 4-7
                    ulonglong2 sp2 = sp[2];   // ch 8-11
                    ulonglong2 sp3 = sp[3];   // ch 12-15 (13-15 zero)
                    acc0p[0] = fma2(w0p, sp0.x, acc0p[0]);  acc1p[0] = fma2(w1p, sp0.x, acc1p[0]);
                    acc0p[1] = fma2(w0p, sp0.y, acc0p[1]);  acc1p[1] = fma2(w1p, sp0.y, acc1p[1]);
                    acc0p[2] = fma2(w0p, sp1.x, acc0p[2]);  acc1p[2] = fma2(w1p, sp1.x, acc1p[2]);
                    acc0p[3] = fma2(w0p, sp1.y, acc0p[3]);  acc1p[3] = fma2(w1p, sp1.y, acc1p[3]);
                    acc0p[4] = fma2(w0p, sp2.x, acc0p[4]);  acc1p[4] = fma2(w1p, sp2.x, acc1p[4]);
                    acc0p[5] = fma2(w0p, sp2.y, acc0p[5]);  acc1p[5] = fma2(w1p, sp2.y, acc1p[5]);
                    acc0p[6] = fma2(w0p, sp3.x, acc0p[6]);  acc1p[6] = fma2(w1p, sp3.x, acc1p[6]);
                }
            }
            __syncthreads();
        }

        // Merge half-1 packed partials into half-0 and store
        if (half == 1) {
#pragma unroll
            for (int k = 0; k < 7; k++) {
                s_red[tl][k]     = acc0p[k];
                s_red[tl][7 + k] = acc1p[k];
            }
        }
        __syncthreads();
        if (half == 0) {
            if (valid0) {
#pragma unroll
                for (int k = 0; k < 7; k++) {
                    float2 m = unpack2(add2(acc0p[k], s_red[tl][k]));
                    out[pidx0 * NC + 2*k] = m.x;
                    if (2*k + 1 < NC) out[pidx0 * NC + 2*k + 1] = m.y;
                }
            }
            if (valid1) {
#pragma unroll
                for (int k = 0; k < 7; k++) {
                    float2 m = unpack2(add2(acc1p[k], s_red[tl][7 + k]));
                    out[pidx1 * NC + 2*k] = m.x;
                    if (2*k + 1 < NC) out[pidx1 * NC + 2*k + 1] = m.y;
                }
            }
        }
        __syncthreads();   // protect s_list/s_red before next tile's reset
    }
}

extern "C" void kernel_launch(void* const* d_in, const int* in_sizes, int n_in,
                              void* d_out, int out_size)
{
    const float* pts      = (const float*)d_in[0];   // [1,129600,3]
    const float* means3D  = (const float*)d_in[1];   // [1,2048,3]
    const float* opac     = (const float*)d_in[2];   // [1,2048]
    const float* sem      = (const float*)d_in[3];   // [1,2048,13]
    const float* scales   = (const float*)d_in[4];   // [1,2048,3]
    const float* cov3D    = (const float*)d_in[5];   // [1,2048,3,3]
    const float* origin   = (const float*)d_in[6];   // [3]
    float* out = (float*)d_out;                      // [129600,13] f32

    precompute_kernel<<<(NP + 255) / 256, 256>>>(means3D, opac, sem, scales, cov3D, origin);
    aggregate_kernel<<<NBLOCKS, TPB>>>(pts, origin, out);
}

// round 6
// speedup vs baseline: 1.0123x; 1.0123x over previous
#include <cuda_runtime.h>

#define HH 60
#define WW 60
#define DDZ 36
#define NP 2048
#define NC 13
#define GRID_SZ 0.08f

#define TX 4
#define TY 8
#define TZ 8          // tile z extent (each compute thread: z and z+4)
#define TZS 4
#define TPB 256       // 2 halves x 128 compute lanes
#define HALF 128
#define BATCH 256

#define NTILE_X (HH / TX)                 // 15
#define NTILE_Y ((WW + TY - 1) / TY)      // 8
#define NTILE_Z ((DDZ + TZ - 1) / TZ)     // 5
#define NTILES (NTILE_X * NTILE_Y * NTILE_Z)  // 600
#define NBLOCKS 592                       // 4 per SM on 148 SMs

// Per-Gaussian precomputed scratch (device globals: no allocation allowed)
__device__ int4   g_box[NP];       // bx, by, bz, r
__device__ float4 g_q0[NP];        // -0.5*ixx, -0.5*iyy, -0.5*izz, pad
__device__ float4 g_q1[NP];        // -ixy, -iyz, -ixz, mx
__device__ float2 g_q2[NP];        // my, mz
__device__ float4 g_sem4[NP][4];   // opacity * semantics, padded 13 -> 16
__device__ int    g_ctr;           // dynamic tile queue head

__global__ void precompute_kernel(const float* __restrict__ means3D,
                                  const float* __restrict__ opac,
                                  const float* __restrict__ semantics,
                                  const float* __restrict__ scales,
                                  const float* __restrict__ cov3D,
                                  const float* __restrict__ origin)
{
    int g = blockIdx.x * blockDim.x + threadIdx.x;
    if (g == 0) g_ctr = 0;           // reset dynamic queue every launch
    if (g >= NP) return;

    const float* cv = cov3D + g * 9;
    float a = cv[0], b = cv[4], c = cv[8];
    float d = cv[1], e = cv[5], f = cv[2];
    float det = a * (b * c - e * e) - d * (d * c - e * f) + f * (d * e - b * f);
    float ixx = (b * c - e * e) / det;
    float iyy = (a * c - f * f) / det;
    float izz = (a * b - d * d) / det;
    float ixy = (e * f - d * c) / det;
    float iyz = (d * f - a * e) / det;
    float ixz = (d * e - b * f) / det;

    float ox = origin[0], oy = origin[1], oz = origin[2];
    float mx = means3D[g * 3 + 0];
    float my = means3D[g * 3 + 1];
    float mz = means3D[g * 3 + 2];

    float s = fmaxf(scales[g * 3 + 0], fmaxf(scales[g * 3 + 1], scales[g * 3 + 2]));
    int r = (int)ceilf(s * 3.0f / GRID_SZ);

    g_box[g] = make_int4((int)((mx - ox) / GRID_SZ),
                         (int)((my - oy) / GRID_SZ),
                         (int)((mz - oz) / GRID_SZ), r);
    g_q0[g] = make_float4(-0.5f * ixx, -0.5f * iyy, -0.5f * izz, 0.0f);
    g_q1[g] = make_float4(-ixy, -iyz, -ixz, mx);
    g_q2[g] = make_float2(my, mz);

    float op = opac[g];
    float sv[16];
#pragma unroll
    for (int cc = 0; cc < NC; cc++) sv[cc] = op * semantics[g * NC + cc];
#pragma unroll
    for (int cc = NC; cc < 16; cc++) sv[cc] = 0.0f;
#pragma unroll
    for (int q = 0; q < 4; q++)
        g_sem4[g][q] = make_float4(sv[q*4], sv[q*4+1], sv[q*4+2], sv[q*4+3]);
}

__global__ __launch_bounds__(TPB)
void aggregate_kernel(const float* __restrict__ pts,
                      const float* __restrict__ origin,
                      float* __restrict__ out)
{
    __shared__ int    s_tile;
    __shared__ int    s_cnt;
    __shared__ short  s_list[NP];
    __shared__ int4   s_box[BATCH];
    __shared__ float4 s_q0[BATCH];
    __shared__ float4 s_q1[BATCH];
    __shared__ float2 s_q2[BATCH];
    __shared__ float4 s_sem[BATCH][4];
    __shared__ float  s_red[HALF][2 * NC + 1];   // half-1 partial accumulators

    const int t    = threadIdx.x;
    const int half = t >> 7;             // 0 or 1
    const int tl   = t & (HALF - 1);

    const float ox = origin[0], oy = origin[1], oz = origin[2];

    for (;;) {
        if (t == 0) {
            s_tile = atomicAdd(&g_ctr, 1);
            s_cnt = 0;
        }
        __syncthreads();
        const int tile = s_tile;
        if (tile >= NTILES) break;

        const int bz  = tile % NTILE_Z;
        const int by  = (tile / NTILE_Z) % NTILE_Y;
        const int bxi = tile / (NTILE_Z * NTILE_Y);

        const int tlo_x = bxi * TX;
        const int tlo_y = by * TY;
        const int tlo_z = bz * TZ;
        const int thi_x = tlo_x + TX - 1;
        const int thi_y = min(tlo_y + TY - 1, WW - 1);
        const int thi_z = min(tlo_z + TZ - 1, DDZ - 1);

        // Cooperative coarse cull (all 256 threads)
        for (int g = t; g < NP; g += TPB) {
            int4 bxv = g_box[g];
            bool hit = (bxv.x - bxv.w <= thi_x) && (bxv.x + bxv.w >= tlo_x)
                    && (bxv.y - bxv.w <= thi_y) && (bxv.y + bxv.w >= tlo_y)
                    && (bxv.z - bxv.w <= thi_z) && (bxv.z + bxv.w >= tlo_z);
            if (hit) {
                int pos = atomicAdd(&s_cnt, 1);
                s_list[pos] = (short)g;
            }
        }
        __syncthreads();
        const int nlist = s_cnt;

        // Thread -> voxel pair (same map for both halves)
        const int tz = tl & (TZS - 1);
        const int ty = (tl >> 2) & (TY - 1);
        const int tx = tl >> 5;
        const int x  = tlo_x + tx;
        const int y  = tlo_y + ty;
        const int z0 = tlo_z + tz;
        const int z1 = z0 + TZS;
        const bool valid0 = (y < WW);
        const bool valid1 = valid0 && (z1 < DDZ);

        const int pidx0 = (x * WW + y) * DDZ + z0;
        const int pidx1 = pidx0 + TZS;

        float px = 0.f, py = 0.f, pz0 = 0.f, pz1 = 0.f;
        int pix = -100000, piy = -100000, piz0 = -100000, piz1 = -100000;
        if (valid0) {
            px  = pts[pidx0 * 3 + 0];
            py  = pts[pidx0 * 3 + 1];
            pz0 = pts[pidx0 * 3 + 2];
            pix  = (int)((px - ox) / GRID_SZ);
            piy  = (int)((py - oy) / GRID_SZ);
            piz0 = (int)((pz0 - oz) / GRID_SZ);
            if (valid1) {
                pz1  = pts[pidx1 * 3 + 2];
                piz1 = (int)((pz1 - oz) / GRID_SZ);
            }
        }

        float acc0[NC], acc1[NC];
#pragma unroll
        for (int c = 0; c < NC; c++) { acc0[c] = 0.0f; acc1[c] = 0.0f; }

        for (int base = 0; base < nlist; base += BATCH) {
            const int cnt = min(BATCH, nlist - base);

            if (t < cnt) {
                int g = s_list[base + t];
                s_box[t] = g_box[g];
                s_q0[t]  = g_q0[g];
                s_q1[t]  = g_q1[g];
                s_q2[t]  = g_q2[g];
#pragma unroll
                for (int q = 0; q < 4; q++) s_sem[t][q] = g_sem4[g][q];
            }
            __syncthreads();

            // Each half walks its own stride-2 subset of the staged batch
            for (int i = half; i < cnt; i += 2) {
                const int4 bxv = s_box[i];
                bool ibxy = (abs(pix - bxv.x) <= bxv.w) & (abs(piy - bxv.y) <= bxv.w);
                bool ib0 = ibxy & (abs(piz0 - bxv.z) <= bxv.w);
                bool ib1 = ibxy & (abs(piz1 - bxv.z) <= bxv.w);
                if (__any_sync(0xffffffffu, ib0 | ib1)) {
                    const float4 q1 = s_q1[i];
                    const float2 q2 = s_q2[i];
                    const float4 q0 = s_q0[i];
                    float dx  = px  - q1.w;
                    float dy  = py  - q2.x;
                    float dz0 = pz0 - q2.y;
                    float dz1 = pz1 - q2.y;
                    float exy = fmaf(q0.x * dx, dx, fmaf(q0.y * dy, dy, q1.x * dx * dy));
                    float h   = fmaf(q1.y, dy, q1.z * dx);
                    float e0  = fmaf(fmaf(q0.z, dz0, h), dz0, exy);
                    float e1  = fmaf(fmaf(q0.z, dz1, h), dz1, exy);
                    float w0 = ib0 ? __expf(e0) : 0.0f;
                    float w1 = ib1 ? __expf(e1) : 0.0f;
                    const float4 sA = s_sem[i][0];
                    const float4 sB = s_sem[i][1];
                    const float4 sC = s_sem[i][2];
                    const float4 sD = s_sem[i][3];
                    acc0[0]  = fmaf(w0, sA.x, acc0[0]);   acc1[0]  = fmaf(w1, sA.x, acc1[0]);
                    acc0[1]  = fmaf(w0, sA.y, acc0[1]);   acc1[1]  = fmaf(w1, sA.y, acc1[1]);
                    acc0[2]  = fmaf(w0, sA.z, acc0[2]);   acc1[2]  = fmaf(w1, sA.z, acc1[2]);
                    acc0[3]  = fmaf(w0, sA.w, acc0[3]);   acc1[3]  = fmaf(w1, sA.w, acc1[3]);
                    acc0[4]  = fmaf(w0, sB.x, acc0[4]);   acc1[4]  = fmaf(w1, sB.x, acc1[4]);
                    acc0[5]  = fmaf(w0, sB.y, acc0[5]);   acc1[5]  = fmaf(w1, sB.y, acc1[5]);
                    acc0[6]  = fmaf(w0, sB.z, acc0[6]);   acc1[6]  = fmaf(w1, sB.z, acc1[6]);
                    acc0[7]  = fmaf(w0, sB.w, acc0[7]);   acc1[7]  = fmaf(w1, sB.w, acc1[7]);
                    acc0[8]  = fmaf(w0, sC.x, acc0[8]);   acc1[8]  = fmaf(w1, sC.x, acc1[8]);
                    acc0[9]  = fmaf(w0, sC.y, acc0[9]);   acc1[9]  = fmaf(w1, sC.y, acc1[9]);
                    acc0[10] = fmaf(w0, sC.z, acc0[10]);  acc1[10] = fmaf(w1, sC.z, acc1[10]);
                    acc0[11] = fmaf(w0, sC.w, acc0[11]);  acc1[11] = fmaf(w1, sC.w, acc1[11]);
                    acc0[12] = fmaf(w0, sD.x, acc0[12]);  acc1[12] = fmaf(w1, sD.x, acc1[12]);
                }
            }
            __syncthreads();
        }

        // Merge half-1 partials into half-0 and store
        if (half == 1) {
#pragma unroll
            for (int c = 0; c < NC; c++) {
                s_red[tl][c]      = acc0[c];
                s_red[tl][NC + c] = acc1[c];
            }
        }
        __syncthreads();
        if (half == 0) {
            if (valid0) {
#pragma unroll
                for (int c = 0; c < NC; c++)
                    out[pidx0 * NC + c] = acc0[c] + s_red[tl][c];
            }
            if (valid1) {
#pragma unroll
                for (int c = 0; c < NC; c++)
                    out[pidx1 * NC + c] = acc1[c] + s_red[tl][NC + c];
            }
        }
        __syncthreads();   // protect s_red/s_cnt before next tile
    }
}

extern "C" void kernel_launch(void* const* d_in, const int* in_sizes, int n_in,
                              void* d_out, int out_size)
{
    const float* pts      = (const float*)d_in[0];   // [1,129600,3]
    const float* means3D  = (const float*)d_in[1];   // [1,2048,3]
    const float* opac     = (const float*)d_in[2];   // [1,2048]
    const float* sem      = (const float*)d_in[3];   // [1,2048,13]
    const float* scales   = (const float*)d_in[4];   // [1,2048,3]
    const float* cov3D    = (const float*)d_in[5];   // [1,2048,3,3]
    const float* origin   = (const float*)d_in[6];   // [3]
    float* out = (float*)d_out;                      // [129600,13] f32

    precompute_kernel<<<(NP + 255) / 256, 256>>>(means3D, opac, sem, scales, cov3D, origin);
    aggregate_kernel<<<NBLOCKS, TPB>>>(pts, origin, out);
}

// round 7
// speedup vs baseline: 1.2731x; 1.2577x over previous
#include <cuda_runtime.h>

#define HH 60
#define WW 60
#define DDZ 36
#define NP 2048
#define NC 13
#define GRID_SZ 0.08f

#define TX 4
#define TY 4
#define TZ 8          // tile z extent; each compute lane owns z and z+4
#define TZS 4
#define TPB 128       // 2 halves x 64 compute lanes
#define HALF 64
#define BATCH 128

#define NTILE_X (HH / TX)   // 15
#define NTILE_Y (WW / TY)   // 15
#define NTILE_Z ((DDZ + TZ - 1) / TZ)  // 5

// Per-Gaussian precomputed scratch (device globals: no allocation allowed)
__device__ int4   g_box[NP];       // bx, by, bz, r
__device__ float4 g_q0[NP];        // -0.5*ixx, -0.5*iyy, -0.5*izz, pad
__device__ float4 g_q1[NP];        // -ixy, -iyz, -ixz, mx
__device__ float2 g_q2[NP];        // my, mz
__device__ float4 g_sem4[NP][4];   // opacity * semantics, padded 13 -> 16

__global__ void precompute_kernel(const float* __restrict__ means3D,
                                  const float* __restrict__ opac,
                                  const float* __restrict__ semantics,
                                  const float* __restrict__ scales,
                                  const float* __restrict__ cov3D,
                                  const float* __restrict__ origin)
{
    int g = blockIdx.x * blockDim.x + threadIdx.x;
    if (g >= NP) return;

    const float* cv = cov3D + g * 9;
    float a = cv[0], b = cv[4], c = cv[8];
    float d = cv[1], e = cv[5], f = cv[2];
    float det = a * (b * c - e * e) - d * (d * c - e * f) + f * (d * e - b * f);
    float ixx = (b * c - e * e) / det;
    float iyy = (a * c - f * f) / det;
    float izz = (a * b - d * d) / det;
    float ixy = (e * f - d * c) / det;
    float iyz = (d * f - a * e) / det;
    float ixz = (d * e - b * f) / det;

    float ox = origin[0], oy = origin[1], oz = origin[2];
    float mx = means3D[g * 3 + 0];
    float my = means3D[g * 3 + 1];
    float mz = means3D[g * 3 + 2];

    float s = fmaxf(scales[g * 3 + 0], fmaxf(scales[g * 3 + 1], scales[g * 3 + 2]));
    int r = (int)ceilf(s * 3.0f / GRID_SZ);

    g_box[g] = make_int4((int)((mx - ox) / GRID_SZ),
                         (int)((my - oy) / GRID_SZ),
                         (int)((mz - oz) / GRID_SZ), r);
    g_q0[g] = make_float4(-0.5f * ixx, -0.5f * iyy, -0.5f * izz, 0.0f);
    g_q1[g] = make_float4(-ixy, -iyz, -ixz, mx);
    g_q2[g] = make_float2(my, mz);

    float op = opac[g];
    float sv[16];
#pragma unroll
    for (int cc = 0; cc < NC; cc++) sv[cc] = op * semantics[g * NC + cc];
#pragma unroll
    for (int cc = NC; cc < 16; cc++) sv[cc] = 0.0f;
#pragma unroll
    for (int q = 0; q < 4; q++)
        g_sem4[g][q] = make_float4(sv[q*4], sv[q*4+1], sv[q*4+2], sv[q*4+3]);
}

__global__ __launch_bounds__(TPB, 8)
void aggregate_kernel(const float* __restrict__ pts,
                      const float* __restrict__ origin,
                      float* __restrict__ out)
{
    __shared__ int    s_cnt;
    __shared__ short  s_list[NP];
    __shared__ int4   s_box[BATCH];
    __shared__ float4 s_q0[BATCH];
    __shared__ float4 s_q1[BATCH];
    __shared__ float2 s_q2[BATCH];
    __shared__ float4 s_sem[BATCH][4];
    __shared__ float  s_red[HALF][2 * NC + 1];   // half-1 partial accumulators

    const int t    = threadIdx.x;
    const int half = t >> 6;             // 0 or 1
    const int tl   = t & (HALF - 1);
    const int lane = t & 31;

    if (t == 0) s_cnt = 0;
    __syncthreads();

    const int tlo_x = blockIdx.x * TX;
    const int tlo_y = blockIdx.y * TY;
    const int tlo_z = blockIdx.z * TZ;
    const int thi_x = tlo_x + TX - 1;
    const int thi_y = tlo_y + TY - 1;
    const int thi_z = min(tlo_z + TZ - 1, DDZ - 1);

    // Cooperative coarse cull, warp-aggregated compaction
    for (int g = t; g < NP; g += TPB) {
        int4 bxv = g_box[g];
        bool hit = (bxv.x - bxv.w <= thi_x) && (bxv.x + bxv.w >= tlo_x)
                && (bxv.y - bxv.w <= thi_y) && (bxv.y + bxv.w >= tlo_y)
                && (bxv.z - bxv.w <= thi_z) && (bxv.z + bxv.w >= tlo_z);
        unsigned mask = __ballot_sync(0xffffffffu, hit);
        if (mask) {
            int base;
            if (lane == 0) base = atomicAdd(&s_cnt, __popc(mask));
            base = __shfl_sync(0xffffffffu, base, 0);
            if (hit) {
                int pos = base + __popc(mask & ((1u << lane) - 1u));
                s_list[pos] = (short)g;
            }
        }
    }
    __syncthreads();
    const int nlist = s_cnt;

    // Lane -> voxel pair: tz(2b) | ty(2b) | tx(2b)
    const int tz = tl & (TZS - 1);
    const int ty = (tl >> 2) & (TY - 1);
    const int tx = tl >> 4;
    const int x  = tlo_x + tx;
    const int y  = tlo_y + ty;
    const int z0 = tlo_z + tz;
    const int z1 = z0 + TZS;
    const bool valid1 = (z1 < DDZ);

    const int pidx0 = (x * WW + y) * DDZ + z0;
    const int pidx1 = pidx0 + TZS;

    const float ox = origin[0], oy = origin[1], oz = origin[2];
    const float px  = pts[pidx0 * 3 + 0];
    const float py  = pts[pidx0 * 3 + 1];
    const float pz0 = pts[pidx0 * 3 + 2];
    const int pix  = (int)((px - ox) / GRID_SZ);
    const int piy  = (int)((py - oy) / GRID_SZ);
    const int piz0 = (int)((pz0 - oz) / GRID_SZ);
    float pz1 = 0.f;
    int piz1 = -100000;
    if (valid1) {
        pz1  = pts[pidx1 * 3 + 2];
        piz1 = (int)((pz1 - oz) / GRID_SZ);
    }

    float acc0[NC], acc1[NC];
#pragma unroll
    for (int c = 0; c < NC; c++) { acc0[c] = 0.0f; acc1[c] = 0.0f; }

    for (int base = 0; base < nlist; base += BATCH) {
        const int cnt = min(BATCH, nlist - base);

        if (t < cnt) {
            int g = s_list[base + t];
            s_box[t] = g_box[g];
            s_q0[t]  = g_q0[g];
            s_q1[t]  = g_q1[g];
            s_q2[t]  = g_q2[g];
#pragma unroll
            for (int q = 0; q < 4; q++) s_sem[t][q] = g_sem4[g][q];
        }
        __syncthreads();

        // Each half walks its own stride-2 subset of the staged batch
        for (int i = half; i < cnt; i += 2) {
            const int4 bxv = s_box[i];
            bool ibxy = (abs(pix - bxv.x) <= bxv.w) & (abs(piy - bxv.y) <= bxv.w);
            bool ib0 = ibxy & (abs(piz0 - bxv.z) <= bxv.w);
            bool ib1 = ibxy & (abs(piz1 - bxv.z) <= bxv.w);
            if (__any_sync(0xffffffffu, ib0 | ib1)) {
                const float4 q1 = s_q1[i];
                const float2 q2 = s_q2[i];
                const float4 q0 = s_q0[i];
                float dx  = px  - q1.w;
                float dy  = py  - q2.x;
                float dz0 = pz0 - q2.y;
                float dz1 = pz1 - q2.y;
                float exy = fmaf(q0.x * dx, dx, fmaf(q0.y * dy, dy, q1.x * dx * dy));
                float h   = fmaf(q1.y, dy, q1.z * dx);
                float e0  = fmaf(fmaf(q0.z, dz0, h), dz0, exy);
                float e1  = fmaf(fmaf(q0.z, dz1, h), dz1, exy);
                float w0 = ib0 ? __expf(e0) : 0.0f;
                float w1 = ib1 ? __expf(e1) : 0.0f;
                const float4 sA = s_sem[i][0];
                const float4 sB = s_sem[i][1];
                const float4 sC = s_sem[i][2];
                const float4 sD = s_sem[i][3];
                acc0[0]  = fmaf(w0, sA.x, acc0[0]);   acc1[0]  = fmaf(w1, sA.x, acc1[0]);
                acc0[1]  = fmaf(w0, sA.y, acc0[1]);   acc1[1]  = fmaf(w1, sA.y, acc1[1]);
                acc0[2]  = fmaf(w0, sA.z, acc0[2]);   acc1[2]  = fmaf(w1, sA.z, acc1[2]);
                acc0[3]  = fmaf(w0, sA.w, acc0[3]);   acc1[3]  = fmaf(w1, sA.w, acc1[3]);
                acc0[4]  = fmaf(w0, sB.x, acc0[4]);   acc1[4]  = fmaf(w1, sB.x, acc1[4]);
                acc0[5]  = fmaf(w0, sB.y, acc0[5]);   acc1[5]  = fmaf(w1, sB.y, acc1[5]);
                acc0[6]  = fmaf(w0, sB.z, acc0[6]);   acc1[6]  = fmaf(w1, sB.z, acc1[6]);
                acc0[7]  = fmaf(w0, sB.w, acc0[7]);   acc1[7]  = fmaf(w1, sB.w, acc1[7]);
                acc0[8]  = fmaf(w0, sC.x, acc0[8]);   acc1[8]  = fmaf(w1, sC.x, acc1[8]);
                acc0[9]  = fmaf(w0, sC.y, acc0[9]);   acc1[9]  = fmaf(w1, sC.y, acc1[9]);
                acc0[10] = fmaf(w0, sC.z, acc0[10]);  acc1[10] = fmaf(w1, sC.z, acc1[10]);
                acc0[11] = fmaf(w0, sC.w, acc0[11]);  acc1[11] = fmaf(w1, sC.w, acc1[11]);
                acc0[12] = fmaf(w0, sD.x, acc0[12]);  acc1[12] = fmaf(w1, sD.x, acc1[12]);
            }
        }
        __syncthreads();
    }

    // Merge half-1 partials into half-0 and store
    if (half == 1) {
#pragma unroll
        for (int c = 0; c < NC; c++) {
            s_red[tl][c]      = acc0[c];
            s_red[tl][NC + c] = acc1[c];
        }
    }
    __syncthreads();
    if (half == 0) {
#pragma unroll
        for (int c = 0; c < NC; c++)
            out[pidx0 * NC + c] = acc0[c] + s_red[tl][c];
        if (valid1) {
#pragma unroll
            for (int c = 0; c < NC; c++)
                out[pidx1 * NC + c] = acc1[c] + s_red[tl][NC + c];
        }
    }
}

extern "C" void kernel_launch(void* const* d_in, const int* in_sizes, int n_in,
                              void* d_out, int out_size)
{
    const float* pts      = (const float*)d_in[0];   // [1,129600,3]
    const float* means3D  = (const float*)d_in[1];   // [1,2048,3]
    const float* opac     = (const float*)d_in[2];   // [1,2048]
    const float* sem      = (const float*)d_in[3];   // [1,2048,13]
    const float* scales   = (const float*)d_in[4];   // [1,2048,3]
    const float* cov3D    = (const float*)d_in[5];   // [1,2048,3,3]
    const float* origin   = (const float*)d_in[6];   // [3]
    float* out = (float*)d_out;                      // [129600,13] f32

    precompute_kernel<<<(NP + 255) / 256, 256>>>(means3D, opac, sem, scales, cov3D, origin);

    dim3 grid(NTILE_X, NTILE_Y, NTILE_Z);   // 15, 15, 5 = 1125 blocks
    aggregate_kernel<<<grid, TPB>>>(pts, origin, out);
}